// round 12
// baseline (speedup 1.0000x reference)
#include <cuda_runtime.h>
#include <cuda_fp16.h>

#define TAGSETN 64
#define SEQN    512
#define MIDT    256
#define NTAGS   66
#define STARTS  64
#define STOPS   65
#define LOG2E_F 1.4426950408889634f
#define LN2_F   0.6931471805599453f
#define OFFB    12.0f

__device__ __forceinline__ float ex2f(float x){float r;asm("ex2.approx.ftz.f32 %0, %1;":"=f"(r):"f"(x));return r;}
__device__ __forceinline__ float lg2f(float x){float r;asm("lg2.approx.ftz.f32 %0, %1;":"=f"(r):"f"(x));return r;}

// dual-chain dual-state dot: 16 LDS.128 + 128 HFMA2, fully independent A/B streams
__device__ __forceinline__ void dot2x2(const __half2* bufA, const __half2* bufB,
                                       const __half2* E0, const __half2* E1,
                                       float& sA0, float& sA1, float& sB0, float& sB1)
{
    const uint4* pA = (const uint4*)bufA;
    const uint4* pB = (const uint4*)bufB;
    const __half2 z = __floats2half2_rn(0.f, 0.f);
    __half2 cA0=z,cA1=z,cA2=z,cA3=z, dA0=z,dA1=z,dA2=z,dA3=z;
    __half2 cB0=z,cB1=z,cB2=z,cB3=z, dB0=z,dB1=z,dB2=z,dB3=z;
    #pragma unroll
    for (int q = 0; q < 8; ++q) {
        const uint4 uA = pA[q];
        const uint4 uB = pB[q];
        const __half2 a0 = *(const __half2*)&uA.x, b0 = *(const __half2*)&uB.x;
        const __half2 a1 = *(const __half2*)&uA.y, b1 = *(const __half2*)&uB.y;
        const __half2 a2 = *(const __half2*)&uA.z, b2 = *(const __half2*)&uB.z;
        const __half2 a3 = *(const __half2*)&uA.w, b3 = *(const __half2*)&uB.w;
        cA0 = __hfma2(a0, E0[4*q+0], cA0);  cB0 = __hfma2(b0, E0[4*q+0], cB0);
        dA0 = __hfma2(a0, E1[4*q+0], dA0);  dB0 = __hfma2(b0, E1[4*q+0], dB0);
        cA1 = __hfma2(a1, E0[4*q+1], cA1);  cB1 = __hfma2(b1, E0[4*q+1], cB1);
        dA1 = __hfma2(a1, E1[4*q+1], dA1);  dB1 = __hfma2(b1, E1[4*q+1], dB1);
        cA2 = __hfma2(a2, E0[4*q+2], cA2);  cB2 = __hfma2(b2, E0[4*q+2], cB2);
        dA2 = __hfma2(a2, E1[4*q+2], dA2);  dB2 = __hfma2(b2, E1[4*q+2], dB2);
        cA3 = __hfma2(a3, E0[4*q+3], cA3);  cB3 = __hfma2(b3, E0[4*q+3], cB3);
        dA3 = __hfma2(a3, E1[4*q+3], dA3);  dB3 = __hfma2(b3, E1[4*q+3], dB3);
    }
    const float2 fA0 = __half22float2(__hadd2(__hadd2(cA0,cA1), __hadd2(cA2,cA3)));
    const float2 fA1 = __half22float2(__hadd2(__hadd2(dA0,dA1), __hadd2(dA2,dA3)));
    const float2 fB0 = __half22float2(__hadd2(__hadd2(cB0,cB1), __hadd2(cB2,cB3)));
    const float2 fB1 = __half22float2(__hadd2(__hadd2(dB0,dB1), __hadd2(dB2,dB3)));
    sA0 = fA0.x + fA0.y;  sA1 = fA1.x + fA1.y;
    sB0 = fB0.x + fB0.y;  sB1 = fB1.x + fB1.y;
}

__global__ __launch_bounds__(128, 4)
void crf_dual_kernel(const float* __restrict__ em,
                     const int*   __restrict__ tags,
                     const float* __restrict__ trans,
                     float*       __restrict__ out)
{
    const int blk = blockIdx.x;
    const int tid = threadIdx.x;
    const int w   = tid >> 5;            // 0..3
    const int k   = tid & 31;
    const int j0  = 2 * k, j1 = 2 * k + 1;
    const int isB = w & 1;               // 0 = fwd warp, 1 = bwd warp
    const int bA  = (w >> 1) * 2;        // first batch of the pair (0 or 2)
    const int bB  = bA + 1;

    __shared__ __align__(16) __half2 sbuf[4][2][2][32]; // [batch][dir][parity][k]
    __shared__ float lgA[4][TAGSETN], lgB[4][TAGSETN];
    __shared__ int   stg[4][SEQN];

    const float* emA = em + (size_t)(blk * 4 + bA) * (SEQN * TAGSETN);
    const float* emB = em + (size_t)(blk * 4 + bB) * (SEQN * TAGSETN);

    for (int idx = tid; idx < 4 * SEQN; idx += 128)
        stg[idx >> 9][idx & 511] = tags[(size_t)(blk * 4 + (idx >> 9)) * SEQN + (idx & 511)];
    __syncthreads();

    __half2 E0[32], E1[32];
    if (!isB) {
        #pragma unroll
        for (int r = 0; r < 32; ++r) {
            E0[r] = __floats2half2_rn(__expf(trans[(2*r  )*NTAGS + j0]),
                                      __expf(trans[(2*r+1)*NTAGS + j0]));
            E1[r] = __floats2half2_rn(__expf(trans[(2*r  )*NTAGS + j1]),
                                      __expf(trans[(2*r+1)*NTAGS + j1]));
        }
    } else {
        #pragma unroll
        for (int r = 0; r < 32; ++r) {
            E0[r] = __floats2half2_rn(__expf(trans[j0*NTAGS + 2*r]),
                                      __expf(trans[j0*NTAGS + 2*r + 1]));
            E1[r] = __floats2half2_rn(__expf(trans[j1*NTAGS + 2*r]),
                                      __expf(trans[j1*NTAGS + 2*r + 1]));
        }
    }

    __half2* bufA0 = sbuf[bA][isB][0]; __half2* bufA1 = sbuf[bA][isB][1];
    __half2* bufB0 = sbuf[bB][isB][0]; __half2* bufB1 = sbuf[bB][isB][1];

    float aA0, aA1, aB0, aB1, lbA, lbB, MpA, MpB;
    float2 eA_c, eA_1, eA_2, eB_c, eB_1, eB_2, peA, peB;
    int tgA, tgB;

    if (!isB) {
        // =============== FWD chains for batches bA, bB ===============
        const float Tst0 = __ldg(&trans[STARTS * NTAGS]);
        float lA0 = (emA[j0] + trans[STARTS*NTAGS + j0] - Tst0) * LOG2E_F;
        float lA1 = (emA[j1] + trans[STARTS*NTAGS + j1] - Tst0) * LOG2E_F;
        float lB0 = (emB[j0] + trans[STARTS*NTAGS + j0] - Tst0) * LOG2E_F;
        float lB1 = (emB[j1] + trans[STARTS*NTAGS + j1] - Tst0) * LOG2E_F;
        float mA = fmaxf(lA0, lA1), mB = fmaxf(lB0, lB1);
        #pragma unroll
        for (int o = 16; o; o >>= 1) {
            mA = fmaxf(mA, __shfl_xor_sync(0xffffffffu, mA, o));
            mB = fmaxf(mB, __shfl_xor_sync(0xffffffffu, mB, o));
        }
        MpA = mA; MpB = mB;
        aA0 = ex2f(lA0 - MpA); aA1 = ex2f(lA1 - MpA);
        aB0 = ex2f(lB0 - MpB); aB1 = ex2f(lB1 - MpB);
        lbA = lA0; lbB = lB0;

        eA_c = *(const float2*)(emA + 1*TAGSETN + j0);
        eA_1 = *(const float2*)(emA + 2*TAGSETN + j0);
        eA_2 = *(const float2*)(emA + 3*TAGSETN + j0);
        eB_c = *(const float2*)(emB + 1*TAGSETN + j0);
        eB_1 = *(const float2*)(emB + 2*TAGSETN + j0);
        eB_2 = *(const float2*)(emB + 3*TAGSETN + j0);
        peA = make_float2(ex2f(eA_c.x * LOG2E_F), ex2f(eA_c.y * LOG2E_F));
        peB = make_float2(ex2f(eB_c.x * LOG2E_F), ex2f(eB_c.y * LOG2E_F));
        tgA = stg[bA][1]; tgB = stg[bB][1];

        for (int t = 1; t <= MIDT; ++t) {
            __half2* bA_ = (t & 1) ? bufA1 : bufA0;
            __half2* bB_ = (t & 1) ? bufB1 : bufB0;
            bA_[k] = __floats2half2_rn(aA0, aA1);
            bB_[k] = __floats2half2_rn(aB0, aB1);
            const float MtA = __shfl_sync(0xffffffffu, lbA, 0) + OFFB;
            const float MtB = __shfl_sync(0xffffffffu, lbB, 0) + OFFB;
            __syncwarp();

            const float hbA = ex2f(MpA - MtA);
            const float hbB = ex2f(MpB - MtB);
            float sA0, sA1, sB0, sB1;
            dot2x2(bA_, bB_, E0, E1, sA0, sA1, sB0, sB1);

            const bool mkA = (tgA != 0), mkB = (tgB != 0);
            aA0 = mkA ? sA0 * (peA.x * hbA) : aA0 * hbA;
            aA1 = mkA ? sA1 * (peA.y * hbA) : aA1 * hbA;
            aB0 = mkB ? sB0 * (peB.x * hbB) : aB0 * hbB;
            aB1 = mkB ? sB1 * (peB.y * hbB) : aB1 * hbB;
            lbA = mkA ? (eA_c.x * LOG2E_F + MpA + lg2f(sA0)) : lbA;
            lbB = mkB ? (eB_c.x * LOG2E_F + MpB + lg2f(sB0)) : lbB;
            MpA = MtA; MpB = MtB;

            eA_c = eA_1; eA_1 = eA_2;
            eB_c = eB_1; eB_1 = eB_2;
            const int tn = (t + 3 <= MIDT) ? t + 3 : MIDT;
            eA_2 = *(const float2*)(emA + tn * TAGSETN + j0);
            eB_2 = *(const float2*)(emB + tn * TAGSETN + j0);
            peA = make_float2(ex2f(eA_c.x * LOG2E_F), ex2f(eA_c.y * LOG2E_F));
            peB = make_float2(ex2f(eB_c.x * LOG2E_F), ex2f(eB_c.y * LOG2E_F));
            const int tt = (t + 1 <= MIDT) ? t + 1 : MIDT;
            tgA = stg[bA][tt]; tgB = stg[bB][tt];
        }
        lgA[bA][j0] = lg2f(aA0) + MpA;  lgA[bA][j1] = lg2f(aA1) + MpA;
        lgA[bB][j0] = lg2f(aB0) + MpB;  lgA[bB][j1] = lg2f(aB1) + MpB;
    } else {
        // =============== BWD chains for batches bA, bB ===============
        lbA = 0.f; lbB = 0.f; MpA = 0.f; MpB = 0.f;
        aA0 = aA1 = aB0 = aB1 = 1.f;
        eA_c = *(const float2*)(emA + 511*TAGSETN + j0);
        eA_1 = *(const float2*)(emA + 510*TAGSETN + j0);
        eA_2 = *(const float2*)(emA + 509*TAGSETN + j0);
        eB_c = *(const float2*)(emB + 511*TAGSETN + j0);
        eB_1 = *(const float2*)(emB + 510*TAGSETN + j0);
        eB_2 = *(const float2*)(emB + 509*TAGSETN + j0);
        peA = make_float2(ex2f(eA_c.x * LOG2E_F), ex2f(eA_c.y * LOG2E_F));
        peB = make_float2(ex2f(eB_c.x * LOG2E_F), ex2f(eB_c.y * LOG2E_F));
        tgA = stg[bA][511]; tgB = stg[bB][511];

        for (int t = 511; t >= 257; --t) {
            __half2* bA_ = (t & 1) ? bufA1 : bufA0;
            __half2* bB_ = (t & 1) ? bufB1 : bufB0;
            bA_[k] = __floats2half2_rn(aA0 * peA.x, aA1 * peA.y);
            bB_[k] = __floats2half2_rn(aB0 * peB.x, aB1 * peB.y);
            const float MtA = __shfl_sync(0xffffffffu, lbA, 0) + OFFB;
            const float MtB = __shfl_sync(0xffffffffu, lbB, 0) + OFFB;
            __syncwarp();

            const float hbA = ex2f(MpA - MtA);
            const float hbB = ex2f(MpB - MtB);
            float sA0, sA1, sB0, sB1;
            dot2x2(bA_, bB_, E0, E1, sA0, sA1, sB0, sB1);

            const bool mkA = (tgA != 0), mkB = (tgB != 0);
            aA0 = (mkA ? sA0 : aA0) * hbA;
            aA1 = (mkA ? sA1 : aA1) * hbA;
            aB0 = (mkB ? sB0 : aB0) * hbB;
            aB1 = (mkB ? sB1 : aB1) * hbB;
            lbA = mkA ? (MpA + lg2f(sA0)) : lbA;
            lbB = mkB ? (MpB + lg2f(sB0)) : lbB;
            MpA = MtA; MpB = MtB;

            eA_c = eA_1; eA_1 = eA_2;
            eB_c = eB_1; eB_1 = eB_2;
            const int tn = (t - 3 >= 257) ? t - 3 : 257;
            eA_2 = *(const float2*)(emA + tn * TAGSETN + j0);
            eB_2 = *(const float2*)(emB + tn * TAGSETN + j0);
            peA = make_float2(ex2f(eA_c.x * LOG2E_F), ex2f(eA_c.y * LOG2E_F));
            peB = make_float2(ex2f(eB_c.x * LOG2E_F), ex2f(eB_c.y * LOG2E_F));
            const int tt = (t - 1 >= 257) ? t - 1 : 257;
            tgA = stg[bA][tt]; tgB = stg[bB][tt];
        }
        lgB[bA][j0] = lg2f(aA0) + MpA;  lgB[bA][j1] = lg2f(aA1) + MpA;
        lgB[bB][j0] = lg2f(aB0) + MpB;  lgB[bB][j1] = lg2f(aB1) + MpB;
    }
    __syncthreads();

    // =============== combine: warp w owns batch w ===============
    {
        const int cb = w;
        const float v0 = lgA[cb][j0] + lgB[cb][j0];
        const float v1 = lgA[cb][j1] + lgB[cb][j1];
        float mz = fmaxf(v0, v1);
        #pragma unroll
        for (int o = 16; o; o >>= 1)
            mz = fmaxf(mz, __shfl_xor_sync(0xffffffffu, mz, o));
        float az = ex2f(v0 - mz) + ex2f(v1 - mz);
        #pragma unroll
        for (int o = 16; o; o >>= 1)
            az += __shfl_xor_sync(0xffffffffu, az, o);

        const float* embb = em + (size_t)(blk * 4 + cb) * (SEQN * TAGSETN);
        float acc = 0.f; int cnt = 0;
        #pragma unroll 4
        for (int q = 0; q < 16; ++q) {
            const int t  = k + 32 * q;
            const int tg = stg[cb][t];
            const bool mk = (tg != 0);
            cnt += mk ? 1 : 0;
            if (t == 0) {
                acc += trans[STARTS * NTAGS + tg];
                if (mk) acc += embb[tg];
            } else if (mk) {
                acc += embb[t * TAGSETN + tg] + trans[stg[cb][t-1] * NTAGS + tg];
            }
        }
        #pragma unroll
        for (int o = 16; o; o >>= 1) {
            acc += __shfl_xor_sync(0xffffffffu, acc, o);
            cnt += __shfl_xor_sync(0xffffffffu, cnt, o);
        }
        if (k == 0) {
            const float Tst0  = __ldg(&trans[STARTS * NTAGS]);
            const float Tend0 = __ldg(&trans[STOPS]);
            const float Cuni  = Tst0 + (float)(SEQN - 1) * Tend0;
            const float logz  = Cuni + (mz + lg2f(az)) * LN2_F;
            int last = cnt - 1; if (last < 0) last = 0;
            out[blk * 4 + cb] = acc + trans[stg[cb][last] * NTAGS + STOPS] - logz;
        }
    }
}

extern "C" void kernel_launch(void* const* d_in, const int* in_sizes, int n_in,
                              void* d_out, int out_size)
{
    const float* emissions   = (const float*)d_in[0];
    const int*   tags        = (const int*)d_in[1];
    const float* transitions = (const float*)d_in[2];
    float*       out         = (float*)d_out;

    const int B = in_sizes[1] / SEQN;
    crf_dual_kernel<<<B / 4, 128>>>(emissions, tags, transitions, out);
}